// round 1
// baseline (speedup 1.0000x reference)
#include <cuda_runtime.h>

// ============================================================================
// RFEncoder: 2-layer hetero GATv2 (2 relations, 2 heads, HID=64)
//
// Key math identity used: softmax is shift-invariant, so we skip segment_max:
//   alpha_e = exp(s_e) / sum_{e' -> dst} exp(s_{e'})
// and out[dst] = (sum_e exp(s_e) * xl[src_e]) / denom[dst]
// => ONE edge pass per relation (accumulate num + den with atomics),
//    then a node pass to normalize and head/relation-average.
// ============================================================================

#define NMAX 100000
#define HD   128   // HEADS * HID

__device__ float g_xl [NMAX * HD];
__device__ float g_xr [NMAX * HD];
__device__ float g_num[NMAX * HD];
__device__ float g_den[NMAX * 2];
__device__ float g_acc[NMAX * 64];
__device__ float g_h  [NMAX * 64];

// ---------------------------------------------------------------------------
__global__ void zero_kernel(float4* __restrict__ p, int n4) {
    int i = blockIdx.x * blockDim.x + threadIdx.x;
    if (i < n4) p[i] = make_float4(0.f, 0.f, 0.f, 0.f);
}

// ---------------------------------------------------------------------------
// Layer-1 transform: X [n,2] -> xl, xr [n,128]
__global__ void transform2_kernel(const float* __restrict__ X,
                                  const float* __restrict__ Wl,
                                  const float* __restrict__ bl,
                                  const float* __restrict__ Wr,
                                  const float* __restrict__ br,
                                  float* __restrict__ xl,
                                  float* __restrict__ xr, int n) {
    int i = blockIdx.x * blockDim.x + threadIdx.x;
    if (i >= n * HD) return;
    int node = i >> 7;
    int j    = i & 127;
    float x0 = X[node * 2 + 0];
    float x1 = X[node * 2 + 1];
    xl[i] = fmaf(x1, Wl[HD + j], fmaf(x0, Wl[j], bl[j]));
    xr[i] = fmaf(x1, Wr[HD + j], fmaf(x0, Wr[j], br[j]));
}

// ---------------------------------------------------------------------------
// Layer-2 transform: Y[n,128] = X[n,64] @ W[64,128] + b
// Block: 128 threads, 32-node tile. W staged in smem (32 KB), X tile in smem.
// Register blocking: 4 nodes x 8 cols per thread.
__global__ void __launch_bounds__(128)
transform64_kernel(const float* __restrict__ X,
                   const float* __restrict__ W,
                   const float* __restrict__ b,
                   float* __restrict__ Y, int n) {
    __shared__ float sW[64 * 128];   // 32 KB
    __shared__ float sX[32 * 68];    // padded rows (68 % 4 == 0 -> f4 aligned)

    int tx = threadIdx.x;

    // Stage W (8192 floats = 2048 float4)
    for (int idx = tx * 4; idx < 64 * 128; idx += 128 * 4)
        *(float4*)&sW[idx] = *(const float4*)&W[idx];

    int node0 = blockIdx.x * 32;
    // Stage X tile: 32 rows x 16 float4
    for (int idx = tx; idx < 512; idx += 128) {
        int r  = idx >> 4;
        int c4 = idx & 15;
        float4 v = make_float4(0.f, 0.f, 0.f, 0.f);
        if (node0 + r < n)
            v = *(const float4*)&X[(size_t)(node0 + r) * 64 + c4 * 4];
        *(float4*)&sX[r * 68 + c4 * 4] = v;
    }
    __syncthreads();

    int cg = tx & 15;     // col group: cols [8*cg, 8*cg+8)
    int ng = tx >> 4;     // node group: nodes [4*ng, 4*ng+4) within tile

    float acc[4][8];
    float bj[8];
#pragma unroll
    for (int j = 0; j < 8; j++) bj[j] = b[cg * 8 + j];
#pragma unroll
    for (int m = 0; m < 4; m++)
#pragma unroll
        for (int j = 0; j < 8; j++) acc[m][j] = bj[j];

    for (int k = 0; k < 64; k += 4) {
        float4 xv[4];
#pragma unroll
        for (int m = 0; m < 4; m++)
            xv[m] = *(const float4*)&sX[(ng * 4 + m) * 68 + k];
#pragma unroll
        for (int kk = 0; kk < 4; kk++) {
            float4 w0 = *(const float4*)&sW[(k + kk) * 128 + cg * 8];
            float4 w1 = *(const float4*)&sW[(k + kk) * 128 + cg * 8 + 4];
#pragma unroll
            for (int m = 0; m < 4; m++) {
                float xs = (kk == 0) ? xv[m].x : (kk == 1) ? xv[m].y
                         : (kk == 2) ? xv[m].z : xv[m].w;
                acc[m][0] = fmaf(xs, w0.x, acc[m][0]);
                acc[m][1] = fmaf(xs, w0.y, acc[m][1]);
                acc[m][2] = fmaf(xs, w0.z, acc[m][2]);
                acc[m][3] = fmaf(xs, w0.w, acc[m][3]);
                acc[m][4] = fmaf(xs, w1.x, acc[m][4]);
                acc[m][5] = fmaf(xs, w1.y, acc[m][5]);
                acc[m][6] = fmaf(xs, w1.z, acc[m][6]);
                acc[m][7] = fmaf(xs, w1.w, acc[m][7]);
            }
        }
    }

#pragma unroll
    for (int m = 0; m < 4; m++) {
        int node = node0 + ng * 4 + m;
        if (node < n) {
            float4 o0 = make_float4(acc[m][0], acc[m][1], acc[m][2], acc[m][3]);
            float4 o1 = make_float4(acc[m][4], acc[m][5], acc[m][6], acc[m][7]);
            *(float4*)&Y[(size_t)node * HD + cg * 8]     = o0;
            *(float4*)&Y[(size_t)node * HD + cg * 8 + 4] = o1;
        }
    }
}

// ---------------------------------------------------------------------------
// Fused edge pass: score -> exp -> atomic num/den accumulation.
// One warp per edge. Lane l covers elements 4l..4l+3 of the 128-dim vector
// (lanes 0-15 = head 0, lanes 16-31 = head 1).
__global__ void edge_kernel(const int* __restrict__ src,
                            const int* __restrict__ dst,
                            const float* __restrict__ xl,
                            const float* __restrict__ xr,
                            const float* __restrict__ att,   // [2][64] = 128
                            float* __restrict__ num,         // [n][128]
                            float* __restrict__ den,         // [n][2]
                            int E) {
    const int lane  = threadIdx.x & 31;
    int warp  = (blockIdx.x * blockDim.x + threadIdx.x) >> 5;
    const int nwarp = (gridDim.x * blockDim.x) >> 5;

    const float4 a4 = *(const float4*)&att[lane * 4];   // hoisted

    for (int e = warp; e < E; e += nwarp) {
        int s = src[e];
        int d = dst[e];

        float4 a = *(const float4*)&xl[(size_t)s * HD + lane * 4];
        float4 bvec = *(const float4*)&xr[(size_t)d * HD + lane * 4];

        float v, sc = 0.f;
        v = a.x + bvec.x; v = v > 0.f ? v : 0.2f * v; sc = fmaf(v, a4.x, sc);
        v = a.y + bvec.y; v = v > 0.f ? v : 0.2f * v; sc = fmaf(v, a4.y, sc);
        v = a.z + bvec.z; v = v > 0.f ? v : 0.2f * v; sc = fmaf(v, a4.z, sc);
        v = a.w + bvec.w; v = v > 0.f ? v : 0.2f * v; sc = fmaf(v, a4.w, sc);

        // reduce within each 16-lane (per-head) group
        sc += __shfl_xor_sync(0xffffffffu, sc, 8);
        sc += __shfl_xor_sync(0xffffffffu, sc, 4);
        sc += __shfl_xor_sync(0xffffffffu, sc, 2);
        sc += __shfl_xor_sync(0xffffffffu, sc, 1);

        float ex = expf(sc);   // shift-free softmax (scores are tiny)

        if (lane == 0)  atomicAdd(&den[(size_t)d * 2 + 0], ex);
        if (lane == 16) atomicAdd(&den[(size_t)d * 2 + 1], ex);

        float* np = &num[(size_t)d * HD + lane * 4];
        atomicAdd(np + 0, ex * a.x);
        atomicAdd(np + 1, ex * a.y);
        atomicAdd(np + 2, ex * a.z);
        atomicAdd(np + 3, ex * a.w);
    }
}

// ---------------------------------------------------------------------------
// Per relation: acc[n,c] += 0.25 * (num[n,0,c]/d0 + num[n,1,c]/d1)
// (0.5 head-mean * 0.5 relation-mean)
__global__ void combine_kernel(const float* __restrict__ num,
                               const float* __restrict__ den,
                               float* __restrict__ acc, int n) {
    int i = blockIdx.x * blockDim.x + threadIdx.x;   // over n*16 float4s
    if (i >= n * 16) return;
    int node = i >> 4;
    int c4   = i & 15;
    float r0 = 1.f / (den[node * 2 + 0] + 1e-16f);
    float r1 = 1.f / (den[node * 2 + 1] + 1e-16f);
    float4 n0 = *(const float4*)&num[(size_t)node * HD + c4 * 4];
    float4 n1 = *(const float4*)&num[(size_t)node * HD + 64 + c4 * 4];
    float4 o  = *(float4*)&acc[(size_t)node * 64 + c4 * 4];
    o.x += 0.25f * (n0.x * r0 + n1.x * r1);
    o.y += 0.25f * (n0.y * r0 + n1.y * r1);
    o.z += 0.25f * (n0.z * r0 + n1.z * r1);
    o.w += 0.25f * (n0.w * r0 + n1.w * r1);
    *(float4*)&acc[(size_t)node * 64 + c4 * 4] = o;
}

// ---------------------------------------------------------------------------
// Layer-1 epilogue: h = relu(acc + 0.5*(bias_adj + bias_ray))
__global__ void relu_bias_kernel(const float* __restrict__ acc,
                                 const float* __restrict__ bias,  // [2][64]
                                 float* __restrict__ h, int n) {
    int i = blockIdx.x * blockDim.x + threadIdx.x;
    if (i >= n * 64) return;
    int c = i & 63;
    float v = acc[i] + 0.5f * (bias[c] + bias[64 + c]);
    h[i] = v > 0.f ? v : 0.f;
}

// Layer-2 epilogue: out = acc + 0.5*(bias_adj + bias_ray)
__global__ void bias_out_kernel(const float* __restrict__ acc,
                                const float* __restrict__ bias,
                                float* __restrict__ out, int n) {
    int i = blockIdx.x * blockDim.x + threadIdx.x;
    if (i >= n * 64) return;
    int c = i & 63;
    out[i] = acc[i] + 0.5f * (bias[c] + bias[64 + c]);
}

// ---------------------------------------------------------------------------
extern "C" void kernel_launch(void* const* d_in, const int* in_sizes, int n_in,
                              void* d_out, int out_size) {
    const float* x       = (const float*)d_in[0];
    const int*   e_adj   = (const int*)  d_in[1];
    const int*   e_ray   = (const int*)  d_in[2];
    const float* l1_Wl   = (const float*)d_in[3];
    const float* l1_bl   = (const float*)d_in[4];
    const float* l1_Wr   = (const float*)d_in[5];
    const float* l1_br   = (const float*)d_in[6];
    const float* l1_att  = (const float*)d_in[7];
    const float* l1_bias = (const float*)d_in[8];
    const float* l2_Wl   = (const float*)d_in[9];
    const float* l2_bl   = (const float*)d_in[10];
    const float* l2_Wr   = (const float*)d_in[11];
    const float* l2_br   = (const float*)d_in[12];
    const float* l2_att  = (const float*)d_in[13];
    const float* l2_bias = (const float*)d_in[14];

    const int N = in_sizes[0] / 2;   // x is [N, 2]
    const int E = in_sizes[1] / 2;   // edges are [2, E]

    float *xl, *xr, *num, *den, *acc, *h;
    cudaGetSymbolAddress((void**)&xl,  g_xl);
    cudaGetSymbolAddress((void**)&xr,  g_xr);
    cudaGetSymbolAddress((void**)&num, g_num);
    cudaGetSymbolAddress((void**)&den, g_den);
    cudaGetSymbolAddress((void**)&acc, g_acc);
    cudaGetSymbolAddress((void**)&h,   g_h);

    const int* edges[2] = {e_adj, e_ray};

    const int ZB = 256;
    const int EDGE_BLOCKS = 1184;     // 8 blocks/SM on 148 SMs
    const int EDGE_TPB    = 256;

    // ---------------- Layer 1 ----------------
    zero_kernel<<<(N * 16 + ZB - 1) / ZB, ZB>>>((float4*)acc, N * 16);
    for (int r = 0; r < 2; r++) {
        transform2_kernel<<<(N * 128 + ZB - 1) / ZB, ZB>>>(
            x, l1_Wl + r * 256, l1_bl + r * 128,
               l1_Wr + r * 256, l1_br + r * 128, xl, xr, N);
        zero_kernel<<<(N * 32 + ZB - 1) / ZB, ZB>>>((float4*)num, N * 32);
        zero_kernel<<<(N / 2 + ZB - 1) / ZB, ZB>>>((float4*)den, N / 2);
        edge_kernel<<<EDGE_BLOCKS, EDGE_TPB>>>(
            edges[r], edges[r] + E, xl, xr, l1_att + r * 128, num, den, E);
        combine_kernel<<<(N * 16 + ZB - 1) / ZB, ZB>>>(num, den, acc, N);
    }
    relu_bias_kernel<<<(N * 64 + ZB - 1) / ZB, ZB>>>(acc, l1_bias, h, N);

    // ---------------- Layer 2 ----------------
    zero_kernel<<<(N * 16 + ZB - 1) / ZB, ZB>>>((float4*)acc, N * 16);
    for (int r = 0; r < 2; r++) {
        transform64_kernel<<<(N + 31) / 32, 128>>>(
            h, l2_Wl + r * 64 * 128, l2_bl + r * 128, xl, N);
        transform64_kernel<<<(N + 31) / 32, 128>>>(
            h, l2_Wr + r * 64 * 128, l2_br + r * 128, xr, N);
        zero_kernel<<<(N * 32 + ZB - 1) / ZB, ZB>>>((float4*)num, N * 32);
        zero_kernel<<<(N / 2 + ZB - 1) / ZB, ZB>>>((float4*)den, N / 2);
        edge_kernel<<<EDGE_BLOCKS, EDGE_TPB>>>(
            edges[r], edges[r] + E, xl, xr, l2_att + r * 128, num, den, E);
        combine_kernel<<<(N * 16 + ZB - 1) / ZB, ZB>>>(num, den, acc, N);
    }
    bias_out_kernel<<<(N * 64 + ZB - 1) / ZB, ZB>>>(acc, l2_bias, (float*)d_out, N);
}

// round 2
// speedup vs baseline: 1.7545x; 1.7545x over previous
#include <cuda_runtime.h>

// ============================================================================
// RFEncoder: 2-layer hetero GATv2 (2 relations, 2 heads, HID=64)
//
// R1 strategy: shift-free softmax (scores tiny -> skip segment_max) +
// PULL-based aggregation over a per-destination CSR built on device each call.
// One warp per destination node keeps xr[d], numerator and denominator in
// registers across its in-edge list -> zero float atomics, one fused epilogue.
// ============================================================================

#define NMAX 100000
#define EMAX 800000
#define HD   128   // HEADS * HID

__device__ float g_xl [NMAX * HD];
__device__ float g_xr [NMAX * HD];
__device__ float g_acc[NMAX * 64];
__device__ float g_h  [NMAX * 64];
__device__ int   g_rowptr[2][NMAX + 1];
__device__ int   g_cursor[2][NMAX];      // holds deg after hist, then cursors
__device__ int   g_csrc  [2][EMAX];      // src node per in-edge, grouped by dst

// ---------------------------------------------------------------------------
__global__ void zero_int_kernel(int* __restrict__ p, int n) {
    int i = blockIdx.x * blockDim.x + threadIdx.x;
    if (i < n) p[i] = 0;
}

// deg histogram over destinations
__global__ void hist_kernel(const int* __restrict__ dst, int* __restrict__ deg, int E) {
    int e = blockIdx.x * blockDim.x + threadIdx.x;
    if (e < E) atomicAdd(&deg[dst[e]], 1);
}

// Single-block exclusive scan: deg (in `cursor`) -> rowptr, and cursor := rowptr
__global__ void scan_kernel(int* __restrict__ cursor, int* __restrict__ rowptr,
                            int n) {
    __shared__ int part[1024];
    int t = threadIdx.x;
    int chunk = (n + 1023) / 1024;
    int lo = t * chunk;
    int hi = lo + chunk; if (hi > n) hi = n;

    int s = 0;
    for (int i = lo; i < hi; i++) s += cursor[i];
    part[t] = s;
    __syncthreads();
    // Kogge-Stone inclusive scan
    for (int d = 1; d < 1024; d <<= 1) {
        int v = (t >= d) ? part[t - d] : 0;
        __syncthreads();
        part[t] += v;
        __syncthreads();
    }
    int off = (t == 0) ? 0 : part[t - 1];   // exclusive prefix
    for (int i = lo; i < hi; i++) {
        int dv = cursor[i];
        rowptr[i] = off;
        cursor[i] = off;
        off += dv;
    }
    if (hi == n) rowptr[n] = off;   // == E (all qualifying threads write same)
}

// Scatter: place src id into the dst's slot range
__global__ void scatter_kernel(const int* __restrict__ src, const int* __restrict__ dst,
                               int* __restrict__ cursor, int* __restrict__ csrc, int E) {
    int e = blockIdx.x * blockDim.x + threadIdx.x;
    if (e < E) {
        int pos = atomicAdd(&cursor[dst[e]], 1);
        csrc[pos] = src[e];
    }
}

// ---------------------------------------------------------------------------
// Layer-1 transform: X [n,2] -> xl, xr [n,128]
__global__ void transform2_kernel(const float* __restrict__ X,
                                  const float* __restrict__ Wl,
                                  const float* __restrict__ bl,
                                  const float* __restrict__ Wr,
                                  const float* __restrict__ br,
                                  float* __restrict__ xl,
                                  float* __restrict__ xr, int n) {
    int i = blockIdx.x * blockDim.x + threadIdx.x;
    if (i >= n * HD) return;
    int node = i >> 7;
    int j    = i & 127;
    float x0 = X[node * 2 + 0];
    float x1 = X[node * 2 + 1];
    xl[i] = fmaf(x1, Wl[HD + j], fmaf(x0, Wl[j], bl[j]));
    xr[i] = fmaf(x1, Wr[HD + j], fmaf(x0, Wr[j], br[j]));
}

// ---------------------------------------------------------------------------
// Layer-2 transform: Y[n,128] = X[n,64] @ W[64,128] + b
__global__ void __launch_bounds__(128)
transform64_kernel(const float* __restrict__ X,
                   const float* __restrict__ W,
                   const float* __restrict__ b,
                   float* __restrict__ Y, int n) {
    __shared__ float sW[64 * 128];   // 32 KB
    __shared__ float sX[32 * 68];

    int tx = threadIdx.x;
    for (int idx = tx * 4; idx < 64 * 128; idx += 128 * 4)
        *(float4*)&sW[idx] = *(const float4*)&W[idx];

    int node0 = blockIdx.x * 32;
    for (int idx = tx; idx < 512; idx += 128) {
        int r  = idx >> 4;
        int c4 = idx & 15;
        float4 v = make_float4(0.f, 0.f, 0.f, 0.f);
        if (node0 + r < n)
            v = *(const float4*)&X[(size_t)(node0 + r) * 64 + c4 * 4];
        *(float4*)&sX[r * 68 + c4 * 4] = v;
    }
    __syncthreads();

    int cg = tx & 15;
    int ng = tx >> 4;

    float acc[4][8];
    float bj[8];
#pragma unroll
    for (int j = 0; j < 8; j++) bj[j] = b[cg * 8 + j];
#pragma unroll
    for (int m = 0; m < 4; m++)
#pragma unroll
        for (int j = 0; j < 8; j++) acc[m][j] = bj[j];

    for (int k = 0; k < 64; k += 4) {
        float4 xv[4];
#pragma unroll
        for (int m = 0; m < 4; m++)
            xv[m] = *(const float4*)&sX[(ng * 4 + m) * 68 + k];
#pragma unroll
        for (int kk = 0; kk < 4; kk++) {
            float4 w0 = *(const float4*)&sW[(k + kk) * 128 + cg * 8];
            float4 w1 = *(const float4*)&sW[(k + kk) * 128 + cg * 8 + 4];
#pragma unroll
            for (int m = 0; m < 4; m++) {
                float xs = (kk == 0) ? xv[m].x : (kk == 1) ? xv[m].y
                         : (kk == 2) ? xv[m].z : xv[m].w;
                acc[m][0] = fmaf(xs, w0.x, acc[m][0]);
                acc[m][1] = fmaf(xs, w0.y, acc[m][1]);
                acc[m][2] = fmaf(xs, w0.z, acc[m][2]);
                acc[m][3] = fmaf(xs, w0.w, acc[m][3]);
                acc[m][4] = fmaf(xs, w1.x, acc[m][4]);
                acc[m][5] = fmaf(xs, w1.y, acc[m][5]);
                acc[m][6] = fmaf(xs, w1.z, acc[m][6]);
                acc[m][7] = fmaf(xs, w1.w, acc[m][7]);
            }
        }
    }

#pragma unroll
    for (int m = 0; m < 4; m++) {
        int node = node0 + ng * 4 + m;
        if (node < n) {
            float4 o0 = make_float4(acc[m][0], acc[m][1], acc[m][2], acc[m][3]);
            float4 o1 = make_float4(acc[m][4], acc[m][5], acc[m][6], acc[m][7]);
            *(float4*)&Y[(size_t)node * HD + cg * 8]     = o0;
            *(float4*)&Y[(size_t)node * HD + cg * 8 + 4] = o1;
        }
    }
}

// ---------------------------------------------------------------------------
// PULL aggregation: one warp per destination node.
// Lane l handles components 4l..4l+3 (lanes 0-15 head 0, 16-31 head 1).
// mode 0: out = 0.25 * head_sum(num/den)           (first relation, raw store)
// mode 1: out = accin + contrib + 0.5*(b0+b1), optional ReLU (finalize)
__global__ void __launch_bounds__(256)
pull_kernel(const int* __restrict__ rowptr,
            const int* __restrict__ csrc,
            const float* __restrict__ xl,
            const float* __restrict__ xr,
            const float* __restrict__ att,    // [128]
            const float* __restrict__ accin,  // [n][64] (mode 1)
            const float* __restrict__ bias,   // [2][64] (mode 1)
            float* __restrict__ out,          // [n][64]
            int n, int mode, int relu) {
    int warp = (blockIdx.x * blockDim.x + threadIdx.x) >> 5;
    if (warp >= n) return;
    int lane = threadIdx.x & 31;

    const float4 a4  = *(const float4*)&att[lane * 4];
    const float4 xrv = *(const float4*)&xr[(size_t)warp * HD + lane * 4];

    float4 ns = make_float4(0.f, 0.f, 0.f, 0.f);
    float den = 0.f;

    int beg = rowptr[warp];
    int end = rowptr[warp + 1];
    int s_next = (beg < end) ? csrc[beg] : 0;

    for (int i = beg; i < end; i++) {
        int s = s_next;
        if (i + 1 < end) s_next = csrc[i + 1];

        float4 a = *(const float4*)&xl[(size_t)s * HD + lane * 4];

        float v, sc = 0.f;
        v = a.x + xrv.x; v = v > 0.f ? v : 0.2f * v; sc = fmaf(v, a4.x, sc);
        v = a.y + xrv.y; v = v > 0.f ? v : 0.2f * v; sc = fmaf(v, a4.y, sc);
        v = a.z + xrv.z; v = v > 0.f ? v : 0.2f * v; sc = fmaf(v, a4.z, sc);
        v = a.w + xrv.w; v = v > 0.f ? v : 0.2f * v; sc = fmaf(v, a4.w, sc);

        // per-head (16-lane) reduction
        sc += __shfl_xor_sync(0xffffffffu, sc, 8);
        sc += __shfl_xor_sync(0xffffffffu, sc, 4);
        sc += __shfl_xor_sync(0xffffffffu, sc, 2);
        sc += __shfl_xor_sync(0xffffffffu, sc, 1);

        float ex = expf(sc);
        ns.x = fmaf(ex, a.x, ns.x);
        ns.y = fmaf(ex, a.y, ns.y);
        ns.z = fmaf(ex, a.z, ns.z);
        ns.w = fmaf(ex, a.w, ns.w);
        den += ex;
    }

    float inv = 0.25f / (den + 1e-16f);   // 0.5 head-mean * 0.5 relation-mean
    float4 v;
    v.x = ns.x * inv; v.y = ns.y * inv; v.z = ns.z * inv; v.w = ns.w * inv;

    // combine heads: lane l (<16) += lane l+16
    v.x += __shfl_xor_sync(0xffffffffu, v.x, 16);
    v.y += __shfl_xor_sync(0xffffffffu, v.y, 16);
    v.z += __shfl_xor_sync(0xffffffffu, v.z, 16);
    v.w += __shfl_xor_sync(0xffffffffu, v.w, 16);

    if (lane < 16) {
        size_t o = (size_t)warp * 64 + lane * 4;
        if (mode == 1) {
            float4 p = *(const float4*)&accin[o];
            int c = lane * 4;
            v.x += p.x + 0.5f * (bias[c + 0] + bias[64 + c + 0]);
            v.y += p.y + 0.5f * (bias[c + 1] + bias[64 + c + 1]);
            v.z += p.z + 0.5f * (bias[c + 2] + bias[64 + c + 2]);
            v.w += p.w + 0.5f * (bias[c + 3] + bias[64 + c + 3]);
            if (relu) {
                v.x = v.x > 0.f ? v.x : 0.f;
                v.y = v.y > 0.f ? v.y : 0.f;
                v.z = v.z > 0.f ? v.z : 0.f;
                v.w = v.w > 0.f ? v.w : 0.f;
            }
        }
        *(float4*)&out[o] = v;
    }
}

// ---------------------------------------------------------------------------
extern "C" void kernel_launch(void* const* d_in, const int* in_sizes, int n_in,
                              void* d_out, int out_size) {
    const float* x       = (const float*)d_in[0];
    const int*   e_adj   = (const int*)  d_in[1];
    const int*   e_ray   = (const int*)  d_in[2];
    const float* l1_Wl   = (const float*)d_in[3];
    const float* l1_bl   = (const float*)d_in[4];
    const float* l1_Wr   = (const float*)d_in[5];
    const float* l1_br   = (const float*)d_in[6];
    const float* l1_att  = (const float*)d_in[7];
    const float* l1_bias = (const float*)d_in[8];
    const float* l2_Wl   = (const float*)d_in[9];
    const float* l2_bl   = (const float*)d_in[10];
    const float* l2_Wr   = (const float*)d_in[11];
    const float* l2_br   = (const float*)d_in[12];
    const float* l2_att  = (const float*)d_in[13];
    const float* l2_bias = (const float*)d_in[14];

    const int N = in_sizes[0] / 2;
    const int E = in_sizes[1] / 2;

    float *xl, *xr, *acc, *h;
    int *rowptr, *cursor, *csrc;
    cudaGetSymbolAddress((void**)&xl,     g_xl);
    cudaGetSymbolAddress((void**)&xr,     g_xr);
    cudaGetSymbolAddress((void**)&acc,    g_acc);
    cudaGetSymbolAddress((void**)&h,      g_h);
    cudaGetSymbolAddress((void**)&rowptr, g_rowptr);
    cudaGetSymbolAddress((void**)&cursor, g_cursor);
    cudaGetSymbolAddress((void**)&csrc,   g_csrc);

    const int* edges[2] = {e_adj, e_ray};
    const int ZB = 256;
    const int EB = (E + ZB - 1) / ZB;
    const int PULL_BLOCKS = (N + 7) / 8;   // 8 warps/block

    // ----- CSR build (by destination), both relations -----
    for (int r = 0; r < 2; r++) {
        int* rp = rowptr + r * (NMAX + 1);
        int* cu = cursor + r * NMAX;
        int* cs = csrc   + r * EMAX;
        const int* dst = edges[r] + E;
        zero_int_kernel<<<(N + ZB - 1) / ZB, ZB>>>(cu, N);
        hist_kernel<<<EB, ZB>>>(dst, cu, E);
        scan_kernel<<<1, 1024>>>(cu, rp, N);
        scatter_kernel<<<EB, ZB>>>(edges[r], dst, cu, cs, E);
    }

    // ----- Layer 1 -----
    for (int r = 0; r < 2; r++) {
        transform2_kernel<<<(N * HD + ZB - 1) / ZB, ZB>>>(
            x, l1_Wl + r * 2 * HD, l1_bl + r * HD,
               l1_Wr + r * 2 * HD, l1_br + r * HD, xl, xr, N);
        pull_kernel<<<PULL_BLOCKS, 256>>>(
            rowptr + r * (NMAX + 1), csrc + r * EMAX, xl, xr,
            l1_att + r * HD, acc, l1_bias,
            (r == 0) ? acc : h, N, r, /*relu=*/1);
    }

    // ----- Layer 2 -----
    for (int r = 0; r < 2; r++) {
        transform64_kernel<<<(N + 31) / 32, 128>>>(
            h, l2_Wl + r * 64 * HD, l2_bl + r * HD, xl, N);
        transform64_kernel<<<(N + 31) / 32, 128>>>(
            h, l2_Wr + r * 64 * HD, l2_br + r * HD, xr, N);
        pull_kernel<<<PULL_BLOCKS, 256>>>(
            rowptr + r * (NMAX + 1), csrc + r * EMAX, xl, xr,
            l2_att + r * HD, acc, l2_bias,
            (r == 0) ? acc : (float*)d_out, N, r, /*relu=*/0);
    }
}

// round 3
// speedup vs baseline: 2.2108x; 1.2601x over previous
#include <cuda_runtime.h>

// ============================================================================
// RFEncoder: 2-layer hetero GATv2 (2 relations, 2 heads, HID=64)
//
// Shift-free softmax + pull-based CSR aggregation. R2: 4-deep software
// pipelining in the pull loop (MLP 1 -> 4), consolidated transform and CSR
// launches, all 4 projection buffers kept live so each phase is one launch.
// ============================================================================

#define NMAX 100000
#define EMAX 800000
#define HD   128   // HEADS * HID

__device__ float g_proj[4][NMAX * HD];   // xl0, xr0, xl1, xr1
__device__ float g_acc [NMAX * 64];
__device__ float g_h   [NMAX * 64];
__device__ int   g_rowptr[2][NMAX + 1];
__device__ int   g_cursor[2][NMAX];
__device__ int   g_csrc  [2][EMAX];

// ---------------------------------------------------------------------------
// CSR build, both relations batched via blockIdx.y
__global__ void zero2_kernel(int* __restrict__ cur, int n) {
    int i = blockIdx.x * blockDim.x + threadIdx.x;
    if (i < n) { cur[i] = 0; cur[NMAX + i] = 0; }
}

__global__ void hist2_kernel(const int* __restrict__ dst0,
                             const int* __restrict__ dst1,
                             int* __restrict__ cur, int E) {
    int e = blockIdx.x * blockDim.x + threadIdx.x;
    if (e >= E) return;
    const int* d = blockIdx.y ? dst1 : dst0;
    atomicAdd(&cur[blockIdx.y * NMAX + d[e]], 1);
}

__global__ void scan2_kernel(int* __restrict__ cursor, int* __restrict__ rowptr,
                             int n) {
    __shared__ int part[1024];
    int r = blockIdx.x;
    int* cur = cursor + r * NMAX;
    int* rp  = rowptr + r * (NMAX + 1);
    int t = threadIdx.x;
    int chunk = (n + 1023) / 1024;
    int lo = t * chunk;
    int hi = lo + chunk; if (hi > n) hi = n;

    int s = 0;
    for (int i = lo; i < hi; i++) s += cur[i];
    part[t] = s;
    __syncthreads();
    for (int d = 1; d < 1024; d <<= 1) {
        int v = (t >= d) ? part[t - d] : 0;
        __syncthreads();
        part[t] += v;
        __syncthreads();
    }
    int off = (t == 0) ? 0 : part[t - 1];
    for (int i = lo; i < hi; i++) {
        int dv = cur[i];
        rp[i] = off;
        cur[i] = off;
        off += dv;
    }
    if (hi == n) rp[n] = off;
}

__global__ void scatter2_kernel(const int* __restrict__ ea,
                                const int* __restrict__ er,
                                int* __restrict__ cursor,
                                int* __restrict__ csrc, int E) {
    int e = blockIdx.x * blockDim.x + threadIdx.x;
    if (e >= E) return;
    int r = blockIdx.y;
    const int* edges = r ? er : ea;
    int pos = atomicAdd(&cursor[r * NMAX + edges[E + e]], 1);
    csrc[r * EMAX + pos] = edges[e];
}

// ---------------------------------------------------------------------------
// Layer-1: X[n,2] -> all 4 projections in one pass
__global__ void transform2_all_kernel(const float* __restrict__ X,
                                      const float* __restrict__ Wl,  // [2][2][128]
                                      const float* __restrict__ bl,  // [2][128]
                                      const float* __restrict__ Wr,
                                      const float* __restrict__ br,
                                      float* __restrict__ proj, int n) {
    int i = blockIdx.x * blockDim.x + threadIdx.x;
    if (i >= n * HD) return;
    int node = i >> 7;
    int j    = i & 127;
    float x0 = X[node * 2 + 0];
    float x1 = X[node * 2 + 1];
    // r=0
    proj[i]                       = fmaf(x1, Wl[HD + j], fmaf(x0, Wl[j], bl[j]));
    proj[(size_t)NMAX * HD + i]   = fmaf(x1, Wr[HD + j], fmaf(x0, Wr[j], br[j]));
    // r=1
    const float* Wl1 = Wl + 2 * HD; const float* bl1 = bl + HD;
    const float* Wr1 = Wr + 2 * HD; const float* br1 = br + HD;
    proj[(size_t)2 * NMAX * HD + i] = fmaf(x1, Wl1[HD + j], fmaf(x0, Wl1[j], bl1[j]));
    proj[(size_t)3 * NMAX * HD + i] = fmaf(x1, Wr1[HD + j], fmaf(x0, Wr1[j], br1[j]));
}

// ---------------------------------------------------------------------------
// Layer-2: Y[n,128] = X[n,64] @ W[64,128] + b ; blockIdx.y selects one of the
// 4 (W, b, out) triples: {Wl r0, Wr r0, Wl r1, Wr r1}.
__global__ void __launch_bounds__(128)
transform64_all_kernel(const float* __restrict__ X,
                       const float* __restrict__ Wl,  // [2][64][128]
                       const float* __restrict__ bl,  // [2][128]
                       const float* __restrict__ Wr,
                       const float* __restrict__ br,
                       float* __restrict__ proj, int n) {
    __shared__ float sW[64 * 128];
    __shared__ float sX[32 * 68];

    int y = blockIdx.y;
    int r = y >> 1;
    const float* W = (y & 1) ? (Wr + r * 64 * HD) : (Wl + r * 64 * HD);
    const float* b = (y & 1) ? (br + r * HD)      : (bl + r * HD);
    float* Y = proj + (size_t)((r << 1) | (y & 1)) * NMAX * HD;
    // layout order in proj: [xl0, xr0, xl1, xr1] -> index = r*2 + (y&1)

    int tx = threadIdx.x;
    for (int idx = tx * 4; idx < 64 * 128; idx += 128 * 4)
        *(float4*)&sW[idx] = *(const float4*)&W[idx];

    int node0 = blockIdx.x * 32;
    for (int idx = tx; idx < 512; idx += 128) {
        int rr = idx >> 4;
        int c4 = idx & 15;
        float4 v = make_float4(0.f, 0.f, 0.f, 0.f);
        if (node0 + rr < n)
            v = *(const float4*)&X[(size_t)(node0 + rr) * 64 + c4 * 4];
        *(float4*)&sX[rr * 68 + c4 * 4] = v;
    }
    __syncthreads();

    int cg = tx & 15;
    int ng = tx >> 4;

    float acc[4][8];
#pragma unroll
    for (int m = 0; m < 4; m++)
#pragma unroll
        for (int j = 0; j < 8; j++) acc[m][j] = b[cg * 8 + j];

    for (int k = 0; k < 64; k += 4) {
        float4 xv[4];
#pragma unroll
        for (int m = 0; m < 4; m++)
            xv[m] = *(const float4*)&sX[(ng * 4 + m) * 68 + k];
#pragma unroll
        for (int kk = 0; kk < 4; kk++) {
            float4 w0 = *(const float4*)&sW[(k + kk) * 128 + cg * 8];
            float4 w1 = *(const float4*)&sW[(k + kk) * 128 + cg * 8 + 4];
#pragma unroll
            for (int m = 0; m < 4; m++) {
                float xs = (kk == 0) ? xv[m].x : (kk == 1) ? xv[m].y
                         : (kk == 2) ? xv[m].z : xv[m].w;
                acc[m][0] = fmaf(xs, w0.x, acc[m][0]);
                acc[m][1] = fmaf(xs, w0.y, acc[m][1]);
                acc[m][2] = fmaf(xs, w0.z, acc[m][2]);
                acc[m][3] = fmaf(xs, w0.w, acc[m][3]);
                acc[m][4] = fmaf(xs, w1.x, acc[m][4]);
                acc[m][5] = fmaf(xs, w1.y, acc[m][5]);
                acc[m][6] = fmaf(xs, w1.z, acc[m][6]);
                acc[m][7] = fmaf(xs, w1.w, acc[m][7]);
            }
        }
    }

#pragma unroll
    for (int m = 0; m < 4; m++) {
        int node = node0 + ng * 4 + m;
        if (node < n) {
            *(float4*)&Y[(size_t)node * HD + cg * 8] =
                make_float4(acc[m][0], acc[m][1], acc[m][2], acc[m][3]);
            *(float4*)&Y[(size_t)node * HD + cg * 8 + 4] =
                make_float4(acc[m][4], acc[m][5], acc[m][6], acc[m][7]);
        }
    }
}

// ---------------------------------------------------------------------------
// PULL aggregation: one warp per destination node, 4-deep pipelined gathers.
// Lane l covers components 4l..4l+3 (lanes 0-15 head 0, 16-31 head 1).
// mode 0: out = 0.25 * head_sum(num/den)
// mode 1: out = accin + contrib + 0.5*(b0+b1), optional ReLU
__global__ void __launch_bounds__(256)
pull_kernel(const int* __restrict__ rowptr,
            const int* __restrict__ csrc,
            const float* __restrict__ xl,
            const float* __restrict__ xr,
            const float* __restrict__ att,
            const float* __restrict__ accin,
            const float* __restrict__ bias,
            float* __restrict__ out,
            int n, int mode, int relu) {
    const unsigned F = 0xffffffffu;
    int node = (blockIdx.x * blockDim.x + threadIdx.x) >> 5;
    if (node >= n) return;
    int lane = threadIdx.x & 31;

    const float4 a4  = *(const float4*)&att[lane * 4];
    const float4 xrv = *(const float4*)&xr[(size_t)node * HD + lane * 4];

    float4 ns = make_float4(0.f, 0.f, 0.f, 0.f);
    float den = 0.f;

    int beg = rowptr[node];
    int end = rowptr[node + 1];

    for (int base = beg; base < end; base += 32) {
        int cnt = end - base; if (cnt > 32) cnt = 32;
        int ld = base + lane; if (ld >= end) ld = end - 1;
        int sv = csrc[ld];

        for (int j = 0; j < cnt; j += 4) {
            int i1 = (j + 1 < cnt) ? j + 1 : j;
            int i2 = (j + 2 < cnt) ? j + 2 : j;
            int i3 = (j + 3 < cnt) ? j + 3 : j;
            int s0 = __shfl_sync(F, sv, j);
            int s1 = __shfl_sync(F, sv, i1);
            int s2 = __shfl_sync(F, sv, i2);
            int s3 = __shfl_sync(F, sv, i3);

            // issue all 4 gathers back-to-back (MLP=4)
            float4 a0 = *(const float4*)&xl[(size_t)s0 * HD + lane * 4];
            float4 a1 = *(const float4*)&xl[(size_t)s1 * HD + lane * 4];
            float4 a2 = *(const float4*)&xl[(size_t)s2 * HD + lane * 4];
            float4 a3 = *(const float4*)&xl[(size_t)s3 * HD + lane * 4];

            float v;
            float sc0 = 0.f, sc1 = 0.f, sc2 = 0.f, sc3 = 0.f;
#define SCORE(sc, a) \
            v = a.x + xrv.x; v = v > 0.f ? v : 0.2f * v; sc = fmaf(v, a4.x, sc); \
            v = a.y + xrv.y; v = v > 0.f ? v : 0.2f * v; sc = fmaf(v, a4.y, sc); \
            v = a.z + xrv.z; v = v > 0.f ? v : 0.2f * v; sc = fmaf(v, a4.z, sc); \
            v = a.w + xrv.w; v = v > 0.f ? v : 0.2f * v; sc = fmaf(v, a4.w, sc);
            SCORE(sc0, a0) SCORE(sc1, a1) SCORE(sc2, a2) SCORE(sc3, a3)
#undef SCORE

#pragma unroll
            for (int d = 8; d >= 1; d >>= 1) {
                sc0 += __shfl_xor_sync(F, sc0, d);
                sc1 += __shfl_xor_sync(F, sc1, d);
                sc2 += __shfl_xor_sync(F, sc2, d);
                sc3 += __shfl_xor_sync(F, sc3, d);
            }

            float e0 = expf(sc0);
            float e1 = (j + 1 < cnt) ? expf(sc1) : 0.f;
            float e2 = (j + 2 < cnt) ? expf(sc2) : 0.f;
            float e3 = (j + 3 < cnt) ? expf(sc3) : 0.f;

            ns.x = fmaf(e0, a0.x, ns.x); ns.y = fmaf(e0, a0.y, ns.y);
            ns.z = fmaf(e0, a0.z, ns.z); ns.w = fmaf(e0, a0.w, ns.w);
            ns.x = fmaf(e1, a1.x, ns.x); ns.y = fmaf(e1, a1.y, ns.y);
            ns.z = fmaf(e1, a1.z, ns.z); ns.w = fmaf(e1, a1.w, ns.w);
            ns.x = fmaf(e2, a2.x, ns.x); ns.y = fmaf(e2, a2.y, ns.y);
            ns.z = fmaf(e2, a2.z, ns.z); ns.w = fmaf(e2, a2.w, ns.w);
            ns.x = fmaf(e3, a3.x, ns.x); ns.y = fmaf(e3, a3.y, ns.y);
            ns.z = fmaf(e3, a3.z, ns.z); ns.w = fmaf(e3, a3.w, ns.w);
            den += e0 + e1 + e2 + e3;
        }
    }

    float inv = 0.25f / (den + 1e-16f);
    float4 v;
    v.x = ns.x * inv; v.y = ns.y * inv; v.z = ns.z * inv; v.w = ns.w * inv;

    v.x += __shfl_xor_sync(F, v.x, 16);
    v.y += __shfl_xor_sync(F, v.y, 16);
    v.z += __shfl_xor_sync(F, v.z, 16);
    v.w += __shfl_xor_sync(F, v.w, 16);

    if (lane < 16) {
        size_t o = (size_t)node * 64 + lane * 4;
        if (mode == 1) {
            float4 p = *(const float4*)&accin[o];
            int c = lane * 4;
            v.x += p.x + 0.5f * (bias[c + 0] + bias[64 + c + 0]);
            v.y += p.y + 0.5f * (bias[c + 1] + bias[64 + c + 1]);
            v.z += p.z + 0.5f * (bias[c + 2] + bias[64 + c + 2]);
            v.w += p.w + 0.5f * (bias[c + 3] + bias[64 + c + 3]);
            if (relu) {
                v.x = v.x > 0.f ? v.x : 0.f;
                v.y = v.y > 0.f ? v.y : 0.f;
                v.z = v.z > 0.f ? v.z : 0.f;
                v.w = v.w > 0.f ? v.w : 0.f;
            }
        }
        *(float4*)&out[o] = v;
    }
}

// ---------------------------------------------------------------------------
extern "C" void kernel_launch(void* const* d_in, const int* in_sizes, int n_in,
                              void* d_out, int out_size) {
    const float* x       = (const float*)d_in[0];
    const int*   e_adj   = (const int*)  d_in[1];
    const int*   e_ray   = (const int*)  d_in[2];
    const float* l1_Wl   = (const float*)d_in[3];
    const float* l1_bl   = (const float*)d_in[4];
    const float* l1_Wr   = (const float*)d_in[5];
    const float* l1_br   = (const float*)d_in[6];
    const float* l1_att  = (const float*)d_in[7];
    const float* l1_bias = (const float*)d_in[8];
    const float* l2_Wl   = (const float*)d_in[9];
    const float* l2_bl   = (const float*)d_in[10];
    const float* l2_Wr   = (const float*)d_in[11];
    const float* l2_br   = (const float*)d_in[12];
    const float* l2_att  = (const float*)d_in[13];
    const float* l2_bias = (const float*)d_in[14];

    const int N = in_sizes[0] / 2;
    const int E = in_sizes[1] / 2;

    float *proj, *acc, *h;
    int *rowptr, *cursor, *csrc;
    cudaGetSymbolAddress((void**)&proj,   g_proj);
    cudaGetSymbolAddress((void**)&acc,    g_acc);
    cudaGetSymbolAddress((void**)&h,      g_h);
    cudaGetSymbolAddress((void**)&rowptr, g_rowptr);
    cudaGetSymbolAddress((void**)&cursor, g_cursor);
    cudaGetSymbolAddress((void**)&csrc,   g_csrc);

    const int ZB = 256;
    const int EB = (E + ZB - 1) / ZB;
    const int PULL_BLOCKS = (N + 7) / 8;

    float* xl0 = proj;
    float* xr0 = proj + (size_t)NMAX * HD;
    float* xl1 = proj + (size_t)2 * NMAX * HD;
    float* xr1 = proj + (size_t)3 * NMAX * HD;

    // ----- CSR build (both relations per launch) -----
    zero2_kernel<<<(N + ZB - 1) / ZB, ZB>>>(cursor, N);
    {
        dim3 g(EB, 2);
        hist2_kernel<<<g, ZB>>>(e_adj + E, e_ray + E, cursor, E);
    }
    scan2_kernel<<<2, 1024>>>(cursor, rowptr, N);
    {
        dim3 g(EB, 2);
        scatter2_kernel<<<g, ZB>>>(e_adj, e_ray, cursor, csrc, E);
    }

    // ----- Layer 1 -----
    transform2_all_kernel<<<(N * HD + ZB - 1) / ZB, ZB>>>(
        x, l1_Wl, l1_bl, l1_Wr, l1_br, proj, N);
    pull_kernel<<<PULL_BLOCKS, 256>>>(
        rowptr, csrc, xl0, xr0, l1_att, acc, l1_bias, acc, N, 0, 0);
    pull_kernel<<<PULL_BLOCKS, 256>>>(
        rowptr + (NMAX + 1), csrc + EMAX, xl1, xr1, l1_att + HD,
        acc, l1_bias, h, N, 1, 1);

    // ----- Layer 2 -----
    {
        dim3 g((N + 31) / 32, 4);
        transform64_all_kernel<<<g, 128>>>(h, l2_Wl, l2_bl, l2_Wr, l2_br, proj, N);
    }
    pull_kernel<<<PULL_BLOCKS, 256>>>(
        rowptr, csrc, xl0, xr0, l2_att, acc, l2_bias, acc, N, 0, 0);
    pull_kernel<<<PULL_BLOCKS, 256>>>(
        rowptr + (NMAX + 1), csrc + EMAX, xl1, xr1, l2_att + HD,
        acc, l2_bias, (float*)d_out, N, 1, 0);
}

// round 4
// speedup vs baseline: 2.4233x; 1.0961x over previous
#include <cuda_runtime.h>

// ============================================================================
// RFEncoder: 2-layer hetero GATv2 (2 relations, 2 heads, HID=64)
//
// R3: (a) layer-1 fully fused into one kernel using linearity of the GATv2
// numerator in the source features (gather 8 B of x[s] per edge instead of
// 512 B of xl[s]; accumulate 3 scalars/head/relation); (b) layer-2 pulls for
// both relations fused into one kernel (no acc round-trip); (c) shift-free
// softmax + CSR pull as before.
// ============================================================================

#define NMAX 100000
#define EMAX 800000
#define HD   128   // HEADS * HID

__device__ float g_proj[4][NMAX * HD];   // xl0, xr0, xl1, xr1 (layer 2 only)
__device__ float g_h   [NMAX * 64];
__device__ int   g_rowptr[2][NMAX + 1];
__device__ int   g_cursor[2][NMAX];
__device__ int   g_csrc  [2][EMAX];

// ---------------------------------------------------------------------------
// CSR build, both relations batched via blockIdx.y
__global__ void zero2_kernel(int* __restrict__ cur, int n) {
    int i = blockIdx.x * blockDim.x + threadIdx.x;
    if (i < n) { cur[i] = 0; cur[NMAX + i] = 0; }
}

__global__ void hist2_kernel(const int* __restrict__ dst0,
                             const int* __restrict__ dst1,
                             int* __restrict__ cur, int E) {
    int e = blockIdx.x * blockDim.x + threadIdx.x;
    if (e >= E) return;
    const int* d = blockIdx.y ? dst1 : dst0;
    atomicAdd(&cur[blockIdx.y * NMAX + d[e]], 1);
}

__global__ void scan2_kernel(int* __restrict__ cursor, int* __restrict__ rowptr,
                             int n) {
    __shared__ int part[1024];
    int r = blockIdx.x;
    int* cur = cursor + r * NMAX;
    int* rp  = rowptr + r * (NMAX + 1);
    int t = threadIdx.x;
    int chunk = (n + 1023) / 1024;
    int lo = t * chunk;
    int hi = lo + chunk; if (hi > n) hi = n;

    int s = 0;
    for (int i = lo; i < hi; i++) s += cur[i];
    part[t] = s;
    __syncthreads();
    for (int d = 1; d < 1024; d <<= 1) {
        int v = (t >= d) ? part[t - d] : 0;
        __syncthreads();
        part[t] += v;
        __syncthreads();
    }
    int off = (t == 0) ? 0 : part[t - 1];
    for (int i = lo; i < hi; i++) {
        int dv = cur[i];
        rp[i] = off;
        cur[i] = off;
        off += dv;
    }
    if (hi == n) rp[n] = off;
}

__global__ void scatter2_kernel(const int* __restrict__ ea,
                                const int* __restrict__ er,
                                int* __restrict__ cursor,
                                int* __restrict__ csrc, int E) {
    int e = blockIdx.x * blockDim.x + threadIdx.x;
    if (e >= E) return;
    int r = blockIdx.y;
    const int* edges = r ? er : ea;
    int pos = atomicAdd(&cursor[r * NMAX + edges[E + e]], 1);
    csrc[r * EMAX + pos] = edges[e];
}

// ---------------------------------------------------------------------------
// Layer 1, fully fused: per warp = destination node, both relations.
// Uses linearity:  num_c = Wl0_c*S0 + Wl1_c*S1 + bl_c*den  with
// S0 = sum(ex*x0[s]), S1 = sum(ex*x1[s]), den = sum(ex)  (per head).
// Lane l covers comps 4l..4l+3 (lanes 0-15 head 0, 16-31 head 1).
__global__ void __launch_bounds__(256)
layer1_fused_kernel(const int* __restrict__ rowptr,   // [2][NMAX+1]
                    const int* __restrict__ csrc,     // [2][EMAX]
                    const float* __restrict__ x,      // [n][2]
                    const float* __restrict__ Wl,     // [2][2][128]
                    const float* __restrict__ bl,     // [2][128]
                    const float* __restrict__ Wr,
                    const float* __restrict__ br,
                    const float* __restrict__ att,    // [2][128]
                    const float* __restrict__ bias,   // [2][64]
                    float* __restrict__ h, int n) {
    const unsigned F = 0xffffffffu;
    int node = (blockIdx.x * blockDim.x + threadIdx.x) >> 5;
    if (node >= n) return;
    int lane = threadIdx.x & 31;

    const float2 xd = ((const float2*)x)[node];

    float4 outv = make_float4(0.f, 0.f, 0.f, 0.f);

#pragma unroll
    for (int r = 0; r < 2; r++) {
        const float4 wl0 = *(const float4*)&Wl[r * 256 + lane * 4];
        const float4 wl1 = *(const float4*)&Wl[r * 256 + HD + lane * 4];
        const float4 blv = *(const float4*)&bl[r * HD + lane * 4];
        const float4 wr0 = *(const float4*)&Wr[r * 256 + lane * 4];
        const float4 wr1 = *(const float4*)&Wr[r * 256 + HD + lane * 4];
        const float4 brv = *(const float4*)&br[r * HD + lane * 4];
        const float4 a4  = *(const float4*)&att[r * HD + lane * 4];

        // xr[d] components for this lane
        float4 xrv;
        xrv.x = fmaf(xd.y, wr1.x, fmaf(xd.x, wr0.x, brv.x));
        xrv.y = fmaf(xd.y, wr1.y, fmaf(xd.x, wr0.y, brv.y));
        xrv.z = fmaf(xd.y, wr1.z, fmaf(xd.x, wr0.z, brv.z));
        xrv.w = fmaf(xd.y, wr1.w, fmaf(xd.x, wr0.w, brv.w));

        const int* rp = rowptr + r * (NMAX + 1);
        const int* cs = csrc   + r * EMAX;
        int beg = rp[node];
        int end = rp[node + 1];

        float S0 = 0.f, S1 = 0.f, den = 0.f;   // head-local (uniform per 16 lanes)

        for (int base = beg; base < end; base += 32) {
            int cnt = end - base; if (cnt > 32) cnt = 32;
            int ld = base + lane; if (ld >= end) ld = end - 1;
            int sv = cs[ld];

            for (int j = 0; j < cnt; j += 4) {
                int i1 = (j + 1 < cnt) ? j + 1 : j;
                int i2 = (j + 2 < cnt) ? j + 2 : j;
                int i3 = (j + 3 < cnt) ? j + 3 : j;
                int s0 = __shfl_sync(F, sv, j);
                int s1 = __shfl_sync(F, sv, i1);
                int s2 = __shfl_sync(F, sv, i2);
                int s3 = __shfl_sync(F, sv, i3);

                // 8-byte gathers (x is ~800 KB: L2-resident broadcasts)
                float2 q0 = ((const float2*)x)[s0];
                float2 q1 = ((const float2*)x)[s1];
                float2 q2 = ((const float2*)x)[s2];
                float2 q3 = ((const float2*)x)[s3];

                float v, sc0 = 0.f, sc1 = 0.f, sc2 = 0.f, sc3 = 0.f;
#define SCORE1(sc, q) \
    v = fmaf(q.y, wl1.x, fmaf(q.x, wl0.x, blv.x)) + xrv.x; \
    v = v > 0.f ? v : 0.2f * v; sc = fmaf(v, a4.x, sc); \
    v = fmaf(q.y, wl1.y, fmaf(q.x, wl0.y, blv.y)) + xrv.y; \
    v = v > 0.f ? v : 0.2f * v; sc = fmaf(v, a4.y, sc); \
    v = fmaf(q.y, wl1.z, fmaf(q.x, wl0.z, blv.z)) + xrv.z; \
    v = v > 0.f ? v : 0.2f * v; sc = fmaf(v, a4.z, sc); \
    v = fmaf(q.y, wl1.w, fmaf(q.x, wl0.w, blv.w)) + xrv.w; \
    v = v > 0.f ? v : 0.2f * v; sc = fmaf(v, a4.w, sc);
                SCORE1(sc0, q0) SCORE1(sc1, q1) SCORE1(sc2, q2) SCORE1(sc3, q3)
#undef SCORE1

#pragma unroll
                for (int d = 8; d >= 1; d >>= 1) {
                    sc0 += __shfl_xor_sync(F, sc0, d);
                    sc1 += __shfl_xor_sync(F, sc1, d);
                    sc2 += __shfl_xor_sync(F, sc2, d);
                    sc3 += __shfl_xor_sync(F, sc3, d);
                }

                float e0 = expf(sc0);
                float e1 = (j + 1 < cnt) ? expf(sc1) : 0.f;
                float e2 = (j + 2 < cnt) ? expf(sc2) : 0.f;
                float e3 = (j + 3 < cnt) ? expf(sc3) : 0.f;

                S0 = fmaf(e0, q0.x, S0); S1 = fmaf(e0, q0.y, S1);
                S0 = fmaf(e1, q1.x, S0); S1 = fmaf(e1, q1.y, S1);
                S0 = fmaf(e2, q2.x, S0); S1 = fmaf(e2, q2.y, S1);
                S0 = fmaf(e3, q3.x, S0); S1 = fmaf(e3, q3.y, S1);
                den += e0 + e1 + e2 + e3;
            }
        }

        // num_c = wl0_c*S0 + wl1_c*S1 + bl_c*den ; contribution = 0.25*num/den
        float inv = 0.25f / (den + 1e-16f);
        outv.x = fmaf(fmaf(S1, wl1.x, fmaf(S0, wl0.x, den * blv.x)), inv, outv.x);
        outv.y = fmaf(fmaf(S1, wl1.y, fmaf(S0, wl0.y, den * blv.y)), inv, outv.y);
        outv.z = fmaf(fmaf(S1, wl1.z, fmaf(S0, wl0.z, den * blv.z)), inv, outv.z);
        outv.w = fmaf(fmaf(S1, wl1.w, fmaf(S0, wl0.w, den * blv.w)), inv, outv.w);
    }

    // fold heads (lane l += lane l+16), add bias, relu, store
    outv.x += __shfl_xor_sync(F, outv.x, 16);
    outv.y += __shfl_xor_sync(F, outv.y, 16);
    outv.z += __shfl_xor_sync(F, outv.z, 16);
    outv.w += __shfl_xor_sync(F, outv.w, 16);

    if (lane < 16) {
        int c = lane * 4;
        outv.x += 0.5f * (bias[c + 0] + bias[64 + c + 0]);
        outv.y += 0.5f * (bias[c + 1] + bias[64 + c + 1]);
        outv.z += 0.5f * (bias[c + 2] + bias[64 + c + 2]);
        outv.w += 0.5f * (bias[c + 3] + bias[64 + c + 3]);
        outv.x = outv.x > 0.f ? outv.x : 0.f;
        outv.y = outv.y > 0.f ? outv.y : 0.f;
        outv.z = outv.z > 0.f ? outv.z : 0.f;
        outv.w = outv.w > 0.f ? outv.w : 0.f;
        *(float4*)&h[(size_t)node * 64 + c] = outv;
    }
}

// ---------------------------------------------------------------------------
// Layer-2 transforms: Y[n,128] = h[n,64] @ W[64,128] + b, 4 GEMMs via grid.y
__global__ void __launch_bounds__(128)
transform64_all_kernel(const float* __restrict__ X,
                       const float* __restrict__ Wl,  // [2][64][128]
                       const float* __restrict__ bl,  // [2][128]
                       const float* __restrict__ Wr,
                       const float* __restrict__ br,
                       float* __restrict__ proj, int n) {
    __shared__ float sW[64 * 128];
    __shared__ float sX[32 * 68];

    int y = blockIdx.y;
    int r = y >> 1;
    const float* W = (y & 1) ? (Wr + r * 64 * HD) : (Wl + r * 64 * HD);
    const float* b = (y & 1) ? (br + r * HD)      : (bl + r * HD);
    float* Y = proj + (size_t)((r << 1) | (y & 1)) * NMAX * HD;

    int tx = threadIdx.x;
    for (int idx = tx * 4; idx < 64 * 128; idx += 128 * 4)
        *(float4*)&sW[idx] = *(const float4*)&W[idx];

    int node0 = blockIdx.x * 32;
    for (int idx = tx; idx < 512; idx += 128) {
        int rr = idx >> 4;
        int c4 = idx & 15;
        float4 v = make_float4(0.f, 0.f, 0.f, 0.f);
        if (node0 + rr < n)
            v = *(const float4*)&X[(size_t)(node0 + rr) * 64 + c4 * 4];
        *(float4*)&sX[rr * 68 + c4 * 4] = v;
    }
    __syncthreads();

    int cg = tx & 15;
    int ng = tx >> 4;

    float acc[4][8];
#pragma unroll
    for (int m = 0; m < 4; m++)
#pragma unroll
        for (int j = 0; j < 8; j++) acc[m][j] = b[cg * 8 + j];

    for (int k = 0; k < 64; k += 4) {
        float4 xv[4];
#pragma unroll
        for (int m = 0; m < 4; m++)
            xv[m] = *(const float4*)&sX[(ng * 4 + m) * 68 + k];
#pragma unroll
        for (int kk = 0; kk < 4; kk++) {
            float4 w0 = *(const float4*)&sW[(k + kk) * 128 + cg * 8];
            float4 w1 = *(const float4*)&sW[(k + kk) * 128 + cg * 8 + 4];
#pragma unroll
            for (int m = 0; m < 4; m++) {
                float xs = (kk == 0) ? xv[m].x : (kk == 1) ? xv[m].y
                         : (kk == 2) ? xv[m].z : xv[m].w;
                acc[m][0] = fmaf(xs, w0.x, acc[m][0]);
                acc[m][1] = fmaf(xs, w0.y, acc[m][1]);
                acc[m][2] = fmaf(xs, w0.z, acc[m][2]);
                acc[m][3] = fmaf(xs, w0.w, acc[m][3]);
                acc[m][4] = fmaf(xs, w1.x, acc[m][4]);
                acc[m][5] = fmaf(xs, w1.y, acc[m][5]);
                acc[m][6] = fmaf(xs, w1.z, acc[m][6]);
                acc[m][7] = fmaf(xs, w1.w, acc[m][7]);
            }
        }
    }

#pragma unroll
    for (int m = 0; m < 4; m++) {
        int node = node0 + ng * 4 + m;
        if (node < n) {
            *(float4*)&Y[(size_t)node * HD + cg * 8] =
                make_float4(acc[m][0], acc[m][1], acc[m][2], acc[m][3]);
            *(float4*)&Y[(size_t)node * HD + cg * 8 + 4] =
                make_float4(acc[m][4], acc[m][5], acc[m][6], acc[m][7]);
        }
    }
}

// ---------------------------------------------------------------------------
// Layer-2 fused pull: per warp = node, both relations sequentially, final
// epilogue (bias, head mean, relation mean) written directly to out.
__global__ void __launch_bounds__(256)
layer2_fused_kernel(const int* __restrict__ rowptr,
                    const int* __restrict__ csrc,
                    const float* __restrict__ proj,   // [4][NMAX*HD]
                    const float* __restrict__ att,    // [2][128]
                    const float* __restrict__ bias,   // [2][64]
                    float* __restrict__ out, int n) {
    const unsigned F = 0xffffffffu;
    int node = (blockIdx.x * blockDim.x + threadIdx.x) >> 5;
    if (node >= n) return;
    int lane = threadIdx.x & 31;

    float4 outv = make_float4(0.f, 0.f, 0.f, 0.f);

#pragma unroll
    for (int r = 0; r < 2; r++) {
        const float* xl = proj + (size_t)(2 * r)     * NMAX * HD;
        const float* xr = proj + (size_t)(2 * r + 1) * NMAX * HD;
        const float4 a4  = *(const float4*)&att[r * HD + lane * 4];
        const float4 xrv = *(const float4*)&xr[(size_t)node * HD + lane * 4];

        const int* rp = rowptr + r * (NMAX + 1);
        const int* cs = csrc   + r * EMAX;
        int beg = rp[node];
        int end = rp[node + 1];

        float4 ns = make_float4(0.f, 0.f, 0.f, 0.f);
        float den = 0.f;

        for (int base = beg; base < end; base += 32) {
            int cnt = end - base; if (cnt > 32) cnt = 32;
            int ld = base + lane; if (ld >= end) ld = end - 1;
            int sv = cs[ld];

            for (int j = 0; j < cnt; j += 4) {
                int i1 = (j + 1 < cnt) ? j + 1 : j;
                int i2 = (j + 2 < cnt) ? j + 2 : j;
                int i3 = (j + 3 < cnt) ? j + 3 : j;
                int s0 = __shfl_sync(F, sv, j);
                int s1 = __shfl_sync(F, sv, i1);
                int s2 = __shfl_sync(F, sv, i2);
                int s3 = __shfl_sync(F, sv, i3);

                float4 a0 = *(const float4*)&xl[(size_t)s0 * HD + lane * 4];
                float4 a1 = *(const float4*)&xl[(size_t)s1 * HD + lane * 4];
                float4 a2 = *(const float4*)&xl[(size_t)s2 * HD + lane * 4];
                float4 a3 = *(const float4*)&xl[(size_t)s3 * HD + lane * 4];

                float v, sc0 = 0.f, sc1 = 0.f, sc2 = 0.f, sc3 = 0.f;
#define SCORE(sc, a) \
    v = a.x + xrv.x; v = v > 0.f ? v : 0.2f * v; sc = fmaf(v, a4.x, sc); \
    v = a.y + xrv.y; v = v > 0.f ? v : 0.2f * v; sc = fmaf(v, a4.y, sc); \
    v = a.z + xrv.z; v = v > 0.f ? v : 0.2f * v; sc = fmaf(v, a4.z, sc); \
    v = a.w + xrv.w; v = v > 0.f ? v : 0.2f * v; sc = fmaf(v, a4.w, sc);
                SCORE(sc0, a0) SCORE(sc1, a1) SCORE(sc2, a2) SCORE(sc3, a3)
#undef SCORE

#pragma unroll
                for (int d = 8; d >= 1; d >>= 1) {
                    sc0 += __shfl_xor_sync(F, sc0, d);
                    sc1 += __shfl_xor_sync(F, sc1, d);
                    sc2 += __shfl_xor_sync(F, sc2, d);
                    sc3 += __shfl_xor_sync(F, sc3, d);
                }

                float e0 = expf(sc0);
                float e1 = (j + 1 < cnt) ? expf(sc1) : 0.f;
                float e2 = (j + 2 < cnt) ? expf(sc2) : 0.f;
                float e3 = (j + 3 < cnt) ? expf(sc3) : 0.f;

                ns.x = fmaf(e0, a0.x, ns.x); ns.y = fmaf(e0, a0.y, ns.y);
                ns.z = fmaf(e0, a0.z, ns.z); ns.w = fmaf(e0, a0.w, ns.w);
                ns.x = fmaf(e1, a1.x, ns.x); ns.y = fmaf(e1, a1.y, ns.y);
                ns.z = fmaf(e1, a1.z, ns.z); ns.w = fmaf(e1, a1.w, ns.w);
                ns.x = fmaf(e2, a2.x, ns.x); ns.y = fmaf(e2, a2.y, ns.y);
                ns.z = fmaf(e2, a2.z, ns.z); ns.w = fmaf(e2, a2.w, ns.w);
                ns.x = fmaf(e3, a3.x, ns.x); ns.y = fmaf(e3, a3.y, ns.y);
                ns.z = fmaf(e3, a3.z, ns.z); ns.w = fmaf(e3, a3.w, ns.w);
                den += e0 + e1 + e2 + e3;
            }
        }

        float inv = 0.25f / (den + 1e-16f);
        outv.x = fmaf(ns.x, inv, outv.x);
        outv.y = fmaf(ns.y, inv, outv.y);
        outv.z = fmaf(ns.z, inv, outv.z);
        outv.w = fmaf(ns.w, inv, outv.w);
    }

    outv.x += __shfl_xor_sync(F, outv.x, 16);
    outv.y += __shfl_xor_sync(F, outv.y, 16);
    outv.z += __shfl_xor_sync(F, outv.z, 16);
    outv.w += __shfl_xor_sync(F, outv.w, 16);

    if (lane < 16) {
        int c = lane * 4;
        outv.x += 0.5f * (bias[c + 0] + bias[64 + c + 0]);
        outv.y += 0.5f * (bias[c + 1] + bias[64 + c + 1]);
        outv.z += 0.5f * (bias[c + 2] + bias[64 + c + 2]);
        outv.w += 0.5f * (bias[c + 3] + bias[64 + c + 3]);
        *(float4*)&out[(size_t)node * 64 + c] = outv;
    }
}

// ---------------------------------------------------------------------------
extern "C" void kernel_launch(void* const* d_in, const int* in_sizes, int n_in,
                              void* d_out, int out_size) {
    const float* x       = (const float*)d_in[0];
    const int*   e_adj   = (const int*)  d_in[1];
    const int*   e_ray   = (const int*)  d_in[2];
    const float* l1_Wl   = (const float*)d_in[3];
    const float* l1_bl   = (const float*)d_in[4];
    const float* l1_Wr   = (const float*)d_in[5];
    const float* l1_br   = (const float*)d_in[6];
    const float* l1_att  = (const float*)d_in[7];
    const float* l1_bias = (const float*)d_in[8];
    const float* l2_Wl   = (const float*)d_in[9];
    const float* l2_bl   = (const float*)d_in[10];
    const float* l2_Wr   = (const float*)d_in[11];
    const float* l2_br   = (const float*)d_in[12];
    const float* l2_att  = (const float*)d_in[13];
    const float* l2_bias = (const float*)d_in[14];

    const int N = in_sizes[0] / 2;
    const int E = in_sizes[1] / 2;

    float *proj, *h;
    int *rowptr, *cursor, *csrc;
    cudaGetSymbolAddress((void**)&proj,   g_proj);
    cudaGetSymbolAddress((void**)&h,      g_h);
    cudaGetSymbolAddress((void**)&rowptr, g_rowptr);
    cudaGetSymbolAddress((void**)&cursor, g_cursor);
    cudaGetSymbolAddress((void**)&csrc,   g_csrc);

    const int ZB = 256;
    const int EB = (E + ZB - 1) / ZB;
    const int PULL_BLOCKS = (N + 7) / 8;

    // ----- CSR build -----
    zero2_kernel<<<(N + ZB - 1) / ZB, ZB>>>(cursor, N);
    {
        dim3 g(EB, 2);
        hist2_kernel<<<g, ZB>>>(e_adj + E, e_ray + E, cursor, E);
    }
    scan2_kernel<<<2, 1024>>>(cursor, rowptr, N);
    {
        dim3 g(EB, 2);
        scatter2_kernel<<<g, ZB>>>(e_adj, e_ray, cursor, csrc, E);
    }

    // ----- Layer 1 (single fused kernel) -----
    layer1_fused_kernel<<<PULL_BLOCKS, 256>>>(
        rowptr, csrc, x, l1_Wl, l1_bl, l1_Wr, l1_br, l1_att, l1_bias, h, N);

    // ----- Layer 2 -----
    {
        dim3 g((N + 31) / 32, 4);
        transform64_all_kernel<<<g, 128>>>(h, l2_Wl, l2_bl, l2_Wr, l2_br, proj, N);
    }
    layer2_fused_kernel<<<PULL_BLOCKS, 256>>>(
        rowptr, csrc, proj, l2_att, l2_bias, (float*)d_out, N);
}